// round 7
// baseline (speedup 1.0000x reference)
#include <cuda_runtime.h>
#include <cuda_fp16.h>
#include <cstdint>

// Problem constants
#define DIMX 768
#define HQ   8
#define HKV  2
#define HD   64
#define SEQ  4096
#define NREP (HQ / HKV)   // 4
#define KSPLIT 4
#define PSTR ((size_t)SEQ * HQ * HD)   // partial ctx stride

// Scratch (allocation-free rule: __device__ globals)
__device__ float  g_Q[SEQ * HQ * HD];           // [4096, 512]  fp32
__device__ float  g_K[SEQ * HKV * HD];          // fp32
__device__ float  g_V[SEQ * HKV * HD];          // fp32
__device__ __half g_Kh[SEQ * HKV * HD];         // half
__device__ __half g_Vt[HKV * HD * SEQ];         // [2][64][4096] half transposed
__device__ float  g_Cpart[KSPLIT * SEQ * HQ * HD];  // 4 ctx partials
__device__ float  g_rspart[KSPLIT * HQ * SEQ];      // 4 rowsum partials

// ===========================================================================
// helpers
// ===========================================================================
__device__ __forceinline__ float f2tf32(float x) {
    uint32_t u;
    asm("cvt.rna.tf32.f32 %0, %1;" : "=r"(u) : "f"(x));
    return __uint_as_float(u);
}
__device__ __forceinline__ float4 tf32x4(float4 v) {
    float4 w;
    w.x = f2tf32(v.x); w.y = f2tf32(v.y); w.z = f2tf32(v.z); w.w = f2tf32(v.w);
    return w;
}
__device__ __forceinline__ void mma_tf32(float* c, const uint32_t* a, const uint32_t* b) {
    asm volatile(
        "mma.sync.aligned.m16n8k8.row.col.f32.tf32.tf32.f32 "
        "{%0,%1,%2,%3}, {%4,%5,%6,%7}, {%8,%9}, {%0,%1,%2,%3};"
        : "+f"(c[0]), "+f"(c[1]), "+f"(c[2]), "+f"(c[3])
        : "r"(a[0]), "r"(a[1]), "r"(a[2]), "r"(a[3]), "r"(b[0]), "r"(b[1]));
}
__device__ __forceinline__ void mma_f16(float* c, const uint32_t* a, uint32_t b0, uint32_t b1) {
    asm volatile(
        "mma.sync.aligned.m16n8k16.row.col.f32.f16.f16.f32 "
        "{%0,%1,%2,%3}, {%4,%5,%6,%7}, {%8,%9}, {%0,%1,%2,%3};"
        : "+f"(c[0]), "+f"(c[1]), "+f"(c[2]), "+f"(c[3])
        : "r"(a[0]), "r"(a[1]), "r"(a[2]), "r"(a[3]), "r"(b0), "r"(b1));
}
__device__ __forceinline__ uint32_t pack2(float a, float b) {
    __half2 h = __floats2half2_rn(a, b);
    return *reinterpret_cast<uint32_t*>(&h);
}
__device__ __forceinline__ float ex2(float x) {
    float y;
    asm("ex2.approx.f32 %0, %1;" : "=f"(y) : "f"(x));
    return y;
}
__device__ __forceinline__ uint32_t fbits(float x) { return __float_as_uint(x); }

// scale baked into Q fragments: 1/sqrt(64) * log2(e)
#define QSCALE 0.1803368801111204f

#define APAD 68
#define BPAD 72
#define HPAD 72   // half tile stride (halves)

// ===========================================================================
// Prep: fp32 K -> half
// ===========================================================================
__global__ void k2h_kernel(const float* __restrict__ K, __half* __restrict__ Kh)
{
    int i = blockIdx.x * 256 + threadIdx.x;
    float4 v = *(const float4*)(K + (size_t)i * 4);
    uint2 o;
    o.x = pack2(v.x, v.y);
    o.y = pack2(v.z, v.w);
    *(uint2*)((char*)Kh + (size_t)i * 8) = o;
}

// ===========================================================================
// Prep: fp32 V [s][kh*64+d] -> half Vt [kh][d][s]
// ===========================================================================
__global__ void vt_kernel(const float* __restrict__ V, __half* __restrict__ Vt)
{
    __shared__ float tile[32][33];
    const int kh = blockIdx.z;
    const int s0 = blockIdx.x * 32;
    const int d0 = blockIdx.y * 32;
    const int tx = threadIdx.x, ty = threadIdx.y;
#pragma unroll
    for (int i = 0; i < 32; i += 8)
        tile[ty + i][tx] = V[(size_t)(s0 + ty + i) * (HKV * HD) + kh * HD + d0 + tx];
    __syncthreads();
#pragma unroll
    for (int i = 0; i < 32; i += 8)
        Vt[(size_t)kh * HD * SEQ + (size_t)(d0 + ty + i) * SEQ + s0 + tx] =
            __float2half_rn(tile[tx][ty + i]);
}

// ===========================================================================
// load persistent Q fragments for 16 rows (scaled by QSCALE)
// ===========================================================================
__device__ __forceinline__ void load_qfrag(
    uint32_t qf[4][4], const float* __restrict__ Q,
    int m0, int h, int wid, int g, int t4)
{
    const float* q0 = Q + (size_t)(m0 + wid * 16 + g) * (HQ * HD) + h * HD;
    const float* q1 = q0 + (size_t)8 * (HQ * HD);
#pragma unroll
    for (int ks = 0; ks < 4; ks++) {
        int c = ks * 16 + t4 * 2;
        qf[ks][0] = pack2(q0[c] * QSCALE, q0[c + 1] * QSCALE);
        qf[ks][1] = pack2(q1[c] * QSCALE, q1[c + 1] * QSCALE);
        qf[ks][2] = pack2(q0[c + 8] * QSCALE, q0[c + 9] * QSCALE);
        qf[ks][3] = pack2(q1[c + 8] * QSCALE, q1[c + 9] * QSCALE);
    }
}

// ===========================================================================
// Pass 1: partial rowsums over a key range. grid (SEQ/128, HQ, KSPLIT)
// ===========================================================================
__global__ __launch_bounds__(256) void rowsum_kernel(
    const float* __restrict__ Q, const __half* __restrict__ Kh,
    float* __restrict__ rspart)
{
    __shared__ __half Ks[128 * HPAD];

    const int t = threadIdx.x, lane = t & 31, wid = t >> 5;
    const int g = lane >> 2, t4 = lane & 3;
    const int m0 = blockIdx.x * 128, h = blockIdx.y, sp = blockIdx.z;
    const int kh = h / NREP;

    uint32_t qf[4][4];
    load_qfrag(qf, Q, m0, h, wid, g, t4);

    float rs0 = 0.f, rs1 = 0.f;
    const int it0 = sp * (SEQ / 128 / KSPLIT);
    const int it1 = it0 + (SEQ / 128 / KSPLIT);

    for (int it = it0; it < it1; it++) {
        const int n0 = it * 128;
        __syncthreads();
#pragma unroll
        for (int i = 0; i < 4; i++) {
            int e = t + i * 256;
            int r = e >> 3, seg = e & 7;
            *(uint4*)&Ks[r * HPAD + seg * 8] =
                *(const uint4*)(Kh + (size_t)(n0 + r) * (HKV * HD) + kh * HD + seg * 8);
        }
        __syncthreads();

#pragma unroll
        for (int jg = 0; jg < 2; jg++) {
            float sacc[8][4];
#pragma unroll
            for (int j = 0; j < 8; j++)
#pragma unroll
                for (int c = 0; c < 4; c++) sacc[j][c] = 0.f;
#pragma unroll
            for (int ks = 0; ks < 4; ks++) {
                const int cb = ks * 16 + t4 * 2;
#pragma unroll
                for (int j = 0; j < 8; j++) {
                    int n = (jg * 8 + j) * 8 + g;
                    uint32_t b0 = *(const uint32_t*)&Ks[n * HPAD + cb];
                    uint32_t b1 = *(const uint32_t*)&Ks[n * HPAD + cb + 8];
                    mma_f16(sacc[j], qf[ks], b0, b1);
                }
            }
#pragma unroll
            for (int j = 0; j < 8; j++) {
                rs0 += ex2(sacc[j][0]) + ex2(sacc[j][1]);
                rs1 += ex2(sacc[j][2]) + ex2(sacc[j][3]);
            }
        }
    }

    rs0 += __shfl_xor_sync(0xffffffffu, rs0, 1);
    rs0 += __shfl_xor_sync(0xffffffffu, rs0, 2);
    rs1 += __shfl_xor_sync(0xffffffffu, rs1, 1);
    rs1 += __shfl_xor_sync(0xffffffffu, rs1, 2);
    if (t4 == 0) {
        float* dst = rspart + (size_t)sp * HQ * SEQ + (size_t)h * SEQ + m0;
        dst[wid * 16 + g] = rs0;
        dst[wid * 16 + g + 8] = rs1;
    }
}

// ===========================================================================
// Pass 2: fused scores + softmax write + PV over a key range.
// grid (SEQ/128, HQ, KSPLIT); ctx partial per split.
// ===========================================================================
__global__ __launch_bounds__(256) void fused_att_kernel(
    const float* __restrict__ Q, const __half* __restrict__ Kh,
    const __half* __restrict__ Vt, const float* __restrict__ rspart,
    float* __restrict__ att, float* __restrict__ Cpart)
{
    __shared__ __half Ks[64 * HPAD];
    __shared__ __half Vs[64 * HPAD];
    __shared__ float sinv[128];

    const int t = threadIdx.x, lane = t & 31, wid = t >> 5;
    const int g = lane >> 2, t4 = lane & 3;
    const int m0 = blockIdx.x * 128, h = blockIdx.y, sp = blockIdx.z;
    const int kh = h / NREP;

    if (t < 128) {
        const float* rp = rspart + (size_t)h * SEQ + m0 + t;
        float s = rp[0];
#pragma unroll
        for (int i = 1; i < KSPLIT; i++) s += rp[(size_t)i * HQ * SEQ];
        sinv[t] = 1.0f / s;
    }

    uint32_t qf[4][4];
    load_qfrag(qf, Q, m0, h, wid, g, t4);
    __syncthreads();

    const int rl = wid * 16 + g;
    const float inv_lo = sinv[rl];
    const float inv_hi = sinv[rl + 8];
    const __half* vth = Vt + (size_t)kh * HD * SEQ;

    float ctx[8][4];
#pragma unroll
    for (int j = 0; j < 8; j++)
#pragma unroll
        for (int c = 0; c < 4; c++) ctx[j][c] = 0.f;

    float* atth = att + (size_t)h * SEQ * SEQ;
    const int it0 = sp * (SEQ / 64 / KSPLIT);
    const int it1 = it0 + (SEQ / 64 / KSPLIT);

    for (int it = it0; it < it1; it++) {
        const int k0 = it * 64;
        __syncthreads();
#pragma unroll
        for (int i = 0; i < 2; i++) {
            int e = t + i * 256;
            int r = e >> 3, seg = e & 7;
            *(uint4*)&Ks[r * HPAD + seg * 8] =
                *(const uint4*)(Kh + (size_t)(k0 + r) * (HKV * HD) + kh * HD + seg * 8);
            *(uint4*)&Vs[r * HPAD + seg * 8] =
                *(const uint4*)(vth + (size_t)r * SEQ + k0 + seg * 8);
        }
        __syncthreads();

        // scores
        float sacc[8][4];
#pragma unroll
        for (int j = 0; j < 8; j++)
#pragma unroll
            for (int c = 0; c < 4; c++) sacc[j][c] = 0.f;

#pragma unroll
        for (int ks = 0; ks < 4; ks++) {
            const int cb = ks * 16 + t4 * 2;
#pragma unroll
            for (int j = 0; j < 8; j++) {
                int n = j * 8 + g;
                uint32_t b0 = *(const uint32_t*)&Ks[n * HPAD + cb];
                uint32_t b1 = *(const uint32_t*)&Ks[n * HPAD + cb + 8];
                mma_f16(sacc[j], qf[ks], b0, b1);
            }
        }

        // epilogue: p = ex2(sacc)*inv -> att, pack to fp16 A-frags
        const size_t rowbase = (size_t)(m0 + rl) * SEQ + k0;
        uint32_t pk[8][2];
#pragma unroll
        for (int j = 0; j < 8; j++) {
            float p0 = ex2(sacc[j][0]) * inv_lo;
            float p1 = ex2(sacc[j][1]) * inv_lo;
            float p2 = ex2(sacc[j][2]) * inv_hi;
            float p3 = ex2(sacc[j][3]) * inv_hi;
            int cj = j * 8 + t4 * 2;
            *(float2*)(atth + rowbase + cj) = make_float2(p0, p1);
            *(float2*)(atth + rowbase + 8 * SEQ + cj) = make_float2(p2, p3);
            pk[j][0] = pack2(p0, p1);
            pk[j][1] = pack2(p2, p3);
        }

        // PV
#pragma unroll
        for (int kc = 0; kc < 4; kc++) {
            uint32_t A[4] = { pk[2 * kc][0], pk[2 * kc][1],
                              pk[2 * kc + 1][0], pk[2 * kc + 1][1] };
            const int kb = kc * 16 + t4 * 2;
#pragma unroll
            for (int jj = 0; jj < 8; jj++) {
                int nn = jj * 8 + g;
                uint32_t b0 = *(const uint32_t*)&Vs[nn * HPAD + kb];
                uint32_t b1 = *(const uint32_t*)&Vs[nn * HPAD + kb + 8];
                mma_f16(ctx[jj], A, b0, b1);
            }
        }
    }

    // store partial context
    float* cp = Cpart + (size_t)sp * PSTR;
#pragma unroll
    for (int jj = 0; jj < 8; jj++) {
        int col = h * HD + jj * 8 + t4 * 2;
        *(float2*)(cp + (size_t)(m0 + rl) * (HQ * HD) + col) =
            make_float2(ctx[jj][0], ctx[jj][1]);
        *(float2*)(cp + (size_t)(m0 + rl + 8) * (HQ * HD) + col) =
            make_float2(ctx[jj][2], ctx[jj][3]);
    }
}

// ===========================================================================
// Projections (tf32 mma). proj_body: plain A; outp_body: A = sum of 4 partials.
// ===========================================================================
#define PJ_AS 0
#define PJ_BS (128 * APAD)
#define PJ_SMEM_BYTES ((PJ_BS + 64 * BPAD) * 4)

__device__ __forceinline__ void proj_mma_stage(
    float* As, float* Bs, float acc[2][4][4],
    int wm, int wn, int g, int t4)
{
#pragma unroll
    for (int ks = 0; ks < 8; ks++) {
        const int kk = ks * 8;
        uint32_t Bf[4][2];
#pragma unroll
        for (int j = 0; j < 4; j++) {
            int n = wn * 32 + j * 8 + g;
            Bf[j][0] = fbits(Bs[(kk + t4) * BPAD + n]);
            Bf[j][1] = fbits(Bs[(kk + t4 + 4) * BPAD + n]);
        }
#pragma unroll
        for (int i = 0; i < 2; i++) {
            int r = wm * 32 + i * 16 + g;
            uint32_t Af[4] = {
                fbits(As[r * APAD + kk + t4]),
                fbits(As[(r + 8) * APAD + kk + t4]),
                fbits(As[r * APAD + kk + t4 + 4]),
                fbits(As[(r + 8) * APAD + kk + t4 + 4]) };
#pragma unroll
            for (int j = 0; j < 4; j++) mma_tf32(acc[i][j], Af, Bf[j]);
        }
    }
}

__device__ __forceinline__ void proj_epilogue(
    float acc[2][4][4], const float* bias, float* C, int ldc,
    int m0, int n0, int wm, int wn, int g, int t4)
{
#pragma unroll
    for (int i = 0; i < 2; i++) {
        int r0 = m0 + wm * 32 + i * 16 + g;
#pragma unroll
        for (int j = 0; j < 4; j++) {
            int col = n0 + wn * 32 + j * 8 + t4 * 2;
            float b0 = bias[col], b1 = bias[col + 1];
            *(float2*)(C + (size_t)r0 * ldc + col) =
                make_float2(acc[i][j][0] + b0, acc[i][j][1] + b1);
            *(float2*)(C + (size_t)(r0 + 8) * ldc + col) =
                make_float2(acc[i][j][2] + b0, acc[i][j][3] + b1);
        }
    }
}

__device__ __forceinline__ void proj_body(
    const float* __restrict__ A, int lda,
    const float* __restrict__ B, int ldb,
    const float* __restrict__ bias,
    float* __restrict__ C, int ldc, int Kdim, int m0, int n0)
{
    extern __shared__ float sm[];
    float* As = sm + PJ_AS;
    float* Bs = sm + PJ_BS;

    const int t = threadIdx.x, lane = t & 31, wid = t >> 5;
    const int wm = wid >> 1, wn = wid & 1;
    const int g = lane >> 2, t4 = lane & 3;

    float acc[2][4][4];
#pragma unroll
    for (int i = 0; i < 2; i++)
#pragma unroll
        for (int j = 0; j < 4; j++)
#pragma unroll
            for (int c = 0; c < 4; c++) acc[i][j][c] = 0.f;

    for (int k0 = 0; k0 < Kdim; k0 += 64) {
        float4 av[8];
#pragma unroll
        for (int i = 0; i < 8; i++) {
            int e = t + i * 256;
            int r = e >> 4, q = e & 15;
            av[i] = tf32x4(*(const float4*)(A + (size_t)(m0 + r) * lda + k0 + q * 4));
        }
        float4 bv[4];
#pragma unroll
        for (int i = 0; i < 4; i++) {
            int e = t + i * 256;
            int r = e >> 4, q = e & 15;
            bv[i] = tf32x4(*(const float4*)(B + (size_t)(k0 + r) * ldb + n0 + q * 4));
        }
        __syncthreads();
#pragma unroll
        for (int i = 0; i < 8; i++) {
            int e = t + i * 256;
            int r = e >> 4, q = e & 15;
            *(float4*)&As[r * APAD + q * 4] = av[i];
        }
#pragma unroll
        for (int i = 0; i < 4; i++) {
            int e = t + i * 256;
            int r = e >> 4, q = e & 15;
            *(float4*)&Bs[r * BPAD + q * 4] = bv[i];
        }
        __syncthreads();
        proj_mma_stage(As, Bs, acc, wm, wn, g, t4);
        __syncthreads();
    }
    proj_epilogue(acc, bias, C, ldc, m0, n0, wm, wn, g, t4);
}

__global__ __launch_bounds__(256, 2) void qkv_proj_kernel(
    const float* __restrict__ x,
    const float* __restrict__ Wq, const float* __restrict__ bq,
    const float* __restrict__ Wk, const float* __restrict__ bk,
    const float* __restrict__ Wv, const float* __restrict__ bv,
    float* __restrict__ Qo, float* __restrict__ Ko, float* __restrict__ Vo)
{
    const int seg = blockIdx.x;
    const int m0 = blockIdx.y * 128;
    const float *W, *bias;
    float* C;
    int ld, n0;
    if (seg < 8)       { W = Wq; bias = bq; C = Qo; ld = HQ * HD;  n0 = seg * 64; }
    else if (seg < 10) { W = Wk; bias = bk; C = Ko; ld = HKV * HD; n0 = (seg - 8) * 64; }
    else               { W = Wv; bias = bv; C = Vo; ld = HKV * HD; n0 = (seg - 10) * 64; }
    proj_body(x, DIMX, W, ld, bias, C, ld, DIMX, m0, n0);
}

// out = (sum_sp Cpart[sp]) @ Wo + bo
__global__ __launch_bounds__(256, 2) void out_proj_kernel(
    const float* __restrict__ Cpart, const float* __restrict__ Wo,
    const float* __restrict__ bo, float* __restrict__ out)
{
    extern __shared__ float sm[];
    float* As = sm + PJ_AS;
    float* Bs = sm + PJ_BS;

    const int t = threadIdx.x, lane = t & 31, wid = t >> 5;
    const int wm = wid >> 1, wn = wid & 1;
    const int g = lane >> 2, t4 = lane & 3;
    const int m0 = blockIdx.y * 128, n0 = blockIdx.x * 64;
    const int lda = HQ * HD;

    float acc[2][4][4];
#pragma unroll
    for (int i = 0; i < 2; i++)
#pragma unroll
        for (int j = 0; j < 4; j++)
#pragma unroll
            for (int c = 0; c < 4; c++) acc[i][j][c] = 0.f;

    for (int k0 = 0; k0 < HQ * HD; k0 += 64) {
        float4 av[8];
#pragma unroll
        for (int i = 0; i < 8; i++) {
            int e = t + i * 256;
            int r = e >> 4, q = e & 15;
            const float* ap = Cpart + (size_t)(m0 + r) * lda + k0 + q * 4;
            float4 v = *(const float4*)ap;
#pragma unroll
            for (int s = 1; s < KSPLIT; s++) {
                float4 w = *(const float4*)(ap + (size_t)s * PSTR);
                v.x += w.x; v.y += w.y; v.z += w.z; v.w += w.w;
            }
            av[i] = tf32x4(v);
        }
        float4 bv[4];
#pragma unroll
        for (int i = 0; i < 4; i++) {
            int e = t + i * 256;
            int r = e >> 4, q = e & 15;
            bv[i] = tf32x4(*(const float4*)(Wo + (size_t)(k0 + r) * DIMX + n0 + q * 4));
        }
        __syncthreads();
#pragma unroll
        for (int i = 0; i < 8; i++) {
            int e = t + i * 256;
            int r = e >> 4, q = e & 15;
            *(float4*)&As[r * APAD + q * 4] = av[i];
        }
#pragma unroll
        for (int i = 0; i < 4; i++) {
            int e = t + i * 256;
            int r = e >> 4, q = e & 15;
            *(float4*)&Bs[r * BPAD + q * 4] = bv[i];
        }
        __syncthreads();
        proj_mma_stage(As, Bs, acc, wm, wn, g, t4);
        __syncthreads();
    }
    proj_epilogue(acc, bo, out, DIMX, m0, n0, wm, wn, g, t4);
}

// ===========================================================================
extern "C" void kernel_launch(void* const* d_in, const int* in_sizes, int n_in,
                              void* d_out, int out_size)
{
    const float* x  = (const float*)d_in[0];
    const float* Wq = (const float*)d_in[1];
    const float* bq = (const float*)d_in[2];
    const float* Wk = (const float*)d_in[3];
    const float* bk = (const float*)d_in[4];
    const float* Wv = (const float*)d_in[5];
    const float* bv = (const float*)d_in[6];
    const float* Wo = (const float*)d_in[7];
    const float* bo = (const float*)d_in[8];

    float* out = (float*)d_out;                 // [4096, 768]
    float* att = out + (size_t)SEQ * DIMX;      // [8, 4096, 4096]

    void* p;
    cudaGetSymbolAddress(&p, g_Q);      float*  Qp  = (float*)p;
    cudaGetSymbolAddress(&p, g_K);      float*  Kp  = (float*)p;
    cudaGetSymbolAddress(&p, g_V);      float*  Vp  = (float*)p;
    cudaGetSymbolAddress(&p, g_Kh);     __half* Khp = (__half*)p;
    cudaGetSymbolAddress(&p, g_Vt);     __half* Vtp = (__half*)p;
    cudaGetSymbolAddress(&p, g_Cpart);  float*  Cpp = (float*)p;
    cudaGetSymbolAddress(&p, g_rspart); float*  Rpp = (float*)p;

    cudaFuncSetAttribute(qkv_proj_kernel,
        cudaFuncAttributeMaxDynamicSharedMemorySize, PJ_SMEM_BYTES);
    cudaFuncSetAttribute(out_proj_kernel,
        cudaFuncAttributeMaxDynamicSharedMemorySize, PJ_SMEM_BYTES);

    dim3 blk(256);

    // QKV projections
    qkv_proj_kernel<<<dim3(12, SEQ / 128), blk, PJ_SMEM_BYTES>>>(
        x, Wq, bq, Wk, bk, Wv, bv, Qp, Kp, Vp);

    // preps
    k2h_kernel<<<(SEQ * HKV * HD) / 4 / 256, blk>>>(Kp, Khp);
    vt_kernel<<<dim3(SEQ / 32, HD / 32, HKV), dim3(32, 8)>>>(Vp, Vtp);

    // Pass 1: partial rowsums (4-way key split)
    rowsum_kernel<<<dim3(SEQ / 128, HQ, KSPLIT), blk>>>(Qp, Khp, Rpp);

    // Pass 2: fused scores + softmax write + PV (4-way key split)
    fused_att_kernel<<<dim3(SEQ / 128, HQ, KSPLIT), blk>>>(
        Qp, Khp, Vtp, Rpp, att, Cpp);

    // out = (sum Cpart) @ Wo + bo
    out_proj_kernel<<<dim3(DIMX / 64, SEQ / 128), blk, PJ_SMEM_BYTES>>>(
        Cpp, Wo, bo, out);
}

// round 8
// speedup vs baseline: 1.0665x; 1.0665x over previous
#include <cuda_runtime.h>
#include <cuda_fp16.h>
#include <cstdint>

// Problem constants
#define DIMX 768
#define HQ   8
#define HKV  2
#define HD   64
#define SEQ  4096
#define NREP (HQ / HKV)   // 4
#define RSPLIT 2          // rowsum key split

// Scratch (allocation-free rule: __device__ globals)
__device__ float  g_Q[SEQ * HQ * HD];           // fp32
__device__ float  g_K[SEQ * HKV * HD];          // fp32
__device__ float  g_V[SEQ * HKV * HD];          // fp32
__device__ __half g_Kh[SEQ * HKV * HD];         // half
__device__ __half g_Vt[HKV * HD * SEQ];         // [2][64][4096] half transposed
__device__ float  g_C[SEQ * HQ * HD];           // context
__device__ float  g_rspart[RSPLIT * HQ * SEQ];  // rowsum partials

// ===========================================================================
// helpers
// ===========================================================================
__device__ __forceinline__ float f2tf32(float x) {
    uint32_t u;
    asm("cvt.rna.tf32.f32 %0, %1;" : "=r"(u) : "f"(x));
    return __uint_as_float(u);
}
__device__ __forceinline__ float4 tf32x4(float4 v) {
    float4 w;
    w.x = f2tf32(v.x); w.y = f2tf32(v.y); w.z = f2tf32(v.z); w.w = f2tf32(v.w);
    return w;
}
__device__ __forceinline__ void mma_tf32(float* c, const uint32_t* a, const uint32_t* b) {
    asm volatile(
        "mma.sync.aligned.m16n8k8.row.col.f32.tf32.tf32.f32 "
        "{%0,%1,%2,%3}, {%4,%5,%6,%7}, {%8,%9}, {%0,%1,%2,%3};"
        : "+f"(c[0]), "+f"(c[1]), "+f"(c[2]), "+f"(c[3])
        : "r"(a[0]), "r"(a[1]), "r"(a[2]), "r"(a[3]), "r"(b[0]), "r"(b[1]));
}
__device__ __forceinline__ void mma_f16(float* c, const uint32_t* a, uint32_t b0, uint32_t b1) {
    asm volatile(
        "mma.sync.aligned.m16n8k16.row.col.f32.f16.f16.f32 "
        "{%0,%1,%2,%3}, {%4,%5,%6,%7}, {%8,%9}, {%0,%1,%2,%3};"
        : "+f"(c[0]), "+f"(c[1]), "+f"(c[2]), "+f"(c[3])
        : "r"(a[0]), "r"(a[1]), "r"(a[2]), "r"(a[3]), "r"(b0), "r"(b1));
}
__device__ __forceinline__ uint32_t pack2(float a, float b) {
    __half2 h = __floats2half2_rn(a, b);
    return *reinterpret_cast<uint32_t*>(&h);
}
__device__ __forceinline__ float ex2(float x) {
    float y;
    asm("ex2.approx.f32 %0, %1;" : "=f"(y) : "f"(x));
    return y;
}
__device__ __forceinline__ void stg_cs_v2(float* p, float a, float b) {
    asm volatile("st.global.cs.v2.f32 [%0], {%1, %2};"
                 :: "l"(p), "f"(a), "f"(b) : "memory");
}
__device__ __forceinline__ uint32_t fbits(float x) { return __float_as_uint(x); }

// scale baked into Q fragments: 1/sqrt(64) * log2(e)
#define QSCALE 0.1803368801111204f

#define APAD 68
#define BPAD 72
#define HPAD 72   // half tile stride (halves)

// ===========================================================================
// Preps
// ===========================================================================
__global__ void k2h_kernel(const float* __restrict__ K, __half* __restrict__ Kh)
{
    int i = blockIdx.x * 256 + threadIdx.x;
    float4 v = *(const float4*)(K + (size_t)i * 4);
    uint2 o;
    o.x = pack2(v.x, v.y);
    o.y = pack2(v.z, v.w);
    *(uint2*)((char*)Kh + (size_t)i * 8) = o;
}

__global__ void vt_kernel(const float* __restrict__ V, __half* __restrict__ Vt)
{
    __shared__ float tile[32][33];
    const int kh = blockIdx.z;
    const int s0 = blockIdx.x * 32;
    const int d0 = blockIdx.y * 32;
    const int tx = threadIdx.x, ty = threadIdx.y;
#pragma unroll
    for (int i = 0; i < 32; i += 8)
        tile[ty + i][tx] = V[(size_t)(s0 + ty + i) * (HKV * HD) + kh * HD + d0 + tx];
    __syncthreads();
#pragma unroll
    for (int i = 0; i < 32; i += 8)
        Vt[(size_t)kh * HD * SEQ + (size_t)(d0 + ty + i) * SEQ + s0 + tx] =
            __float2half_rn(tile[tx][ty + i]);
}

// ===========================================================================
// Q fragment loader (16 rows per warp, scaled)
// ===========================================================================
__device__ __forceinline__ void load_qfrag(
    uint32_t qf[4][4], const float* __restrict__ Q,
    int row0, int h, int g, int t4)
{
    const float* q0 = Q + (size_t)(row0 + g) * (HQ * HD) + h * HD;
    const float* q1 = q0 + (size_t)8 * (HQ * HD);
#pragma unroll
    for (int ks = 0; ks < 4; ks++) {
        int c = ks * 16 + t4 * 2;
        qf[ks][0] = pack2(q0[c] * QSCALE, q0[c + 1] * QSCALE);
        qf[ks][1] = pack2(q1[c] * QSCALE, q1[c + 1] * QSCALE);
        qf[ks][2] = pack2(q0[c + 8] * QSCALE, q0[c + 9] * QSCALE);
        qf[ks][3] = pack2(q1[c + 8] * QSCALE, q1[c + 9] * QSCALE);
    }
}

// ===========================================================================
// Pass 1: partial rowsums. 128 thr, 4 warps x 16 rows = 64-row m-tile.
// grid (SEQ/64, HQ, RSPLIT).
// ===========================================================================
__global__ __launch_bounds__(128) void rowsum_kernel(
    const float* __restrict__ Q, const __half* __restrict__ Kh,
    float* __restrict__ rspart)
{
    __shared__ __half Ks[128 * HPAD];

    const int t = threadIdx.x, lane = t & 31, wid = t >> 5;
    const int g = lane >> 2, t4 = lane & 3;
    const int m0 = blockIdx.x * 64, h = blockIdx.y, sp = blockIdx.z;
    const int kh = h / NREP;

    uint32_t qf[4][4];
    load_qfrag(qf, Q, m0 + wid * 16, h, g, t4);

    float rs0 = 0.f, rs1 = 0.f;
    const int it0 = sp * (SEQ / 128 / RSPLIT);
    const int it1 = it0 + (SEQ / 128 / RSPLIT);

    for (int it = it0; it < it1; it++) {
        const int n0 = it * 128;
        __syncthreads();
#pragma unroll
        for (int i = 0; i < 8; i++) {
            int e = t + i * 128;
            int r = e >> 3, seg = e & 7;
            *(uint4*)&Ks[r * HPAD + seg * 8] =
                *(const uint4*)(Kh + (size_t)(n0 + r) * (HKV * HD) + kh * HD + seg * 8);
        }
        __syncthreads();

#pragma unroll
        for (int jg = 0; jg < 2; jg++) {
            float sacc[8][4];
#pragma unroll
            for (int j = 0; j < 8; j++)
#pragma unroll
                for (int c = 0; c < 4; c++) sacc[j][c] = 0.f;
#pragma unroll
            for (int ks = 0; ks < 4; ks++) {
                const int cb = ks * 16 + t4 * 2;
#pragma unroll
                for (int j = 0; j < 8; j++) {
                    int n = (jg * 8 + j) * 8 + g;
                    uint32_t b0 = *(const uint32_t*)&Ks[n * HPAD + cb];
                    uint32_t b1 = *(const uint32_t*)&Ks[n * HPAD + cb + 8];
                    mma_f16(sacc[j], qf[ks], b0, b1);
                }
            }
#pragma unroll
            for (int j = 0; j < 8; j++) {
                rs0 += ex2(sacc[j][0]) + ex2(sacc[j][1]);
                rs1 += ex2(sacc[j][2]) + ex2(sacc[j][3]);
            }
        }
    }

    rs0 += __shfl_xor_sync(0xffffffffu, rs0, 1);
    rs0 += __shfl_xor_sync(0xffffffffu, rs0, 2);
    rs1 += __shfl_xor_sync(0xffffffffu, rs1, 1);
    rs1 += __shfl_xor_sync(0xffffffffu, rs1, 2);
    if (t4 == 0) {
        float* dst = rspart + (size_t)sp * HQ * SEQ + (size_t)h * SEQ + m0 + wid * 16;
        dst[g] = rs0;
        dst[g + 8] = rs1;
    }
}

// ===========================================================================
// Pass 2: fused scores + softmax write (.cs) + PV.
// 128 thr, 4 warps x 16 rows = 64-row m-tile. grid (SEQ/64, HQ). No k-split.
// ===========================================================================
__global__ __launch_bounds__(128) void fused_att_kernel(
    const float* __restrict__ Q, const __half* __restrict__ Kh,
    const __half* __restrict__ Vt, const float* __restrict__ rspart,
    float* __restrict__ att, float* __restrict__ Ctx)
{
    __shared__ __half Ks[64 * HPAD];
    __shared__ __half Vs[64 * HPAD];
    __shared__ float sinv[64];

    const int t = threadIdx.x, lane = t & 31, wid = t >> 5;
    const int g = lane >> 2, t4 = lane & 3;
    const int m0 = blockIdx.x * 64, h = blockIdx.y;
    const int kh = h / NREP;

    if (t < 64) {
        const float* rp = rspart + (size_t)h * SEQ + m0 + t;
        float s = rp[0];
#pragma unroll
        for (int i = 1; i < RSPLIT; i++) s += rp[(size_t)i * HQ * SEQ];
        sinv[t] = 1.0f / s;
    }

    uint32_t qf[4][4];
    load_qfrag(qf, Q, m0 + wid * 16, h, g, t4);
    __syncthreads();

    const int rl = wid * 16 + g;
    const float inv_lo = sinv[rl];
    const float inv_hi = sinv[rl + 8];
    const __half* vth = Vt + (size_t)kh * HD * SEQ;

    float ctx[8][4];
#pragma unroll
    for (int j = 0; j < 8; j++)
#pragma unroll
        for (int c = 0; c < 4; c++) ctx[j][c] = 0.f;

    float* atth = att + (size_t)h * SEQ * SEQ;

    for (int it = 0; it < SEQ / 64; it++) {
        const int k0 = it * 64;
        __syncthreads();
#pragma unroll
        for (int i = 0; i < 4; i++) {
            int e = t + i * 128;
            int r = e >> 3, seg = e & 7;
            *(uint4*)&Ks[r * HPAD + seg * 8] =
                *(const uint4*)(Kh + (size_t)(k0 + r) * (HKV * HD) + kh * HD + seg * 8);
            *(uint4*)&Vs[r * HPAD + seg * 8] =
                *(const uint4*)(vth + (size_t)r * SEQ + k0 + seg * 8);
        }
        __syncthreads();

        // scores: 16 rows x 64 keys
        float sacc[8][4];
#pragma unroll
        for (int j = 0; j < 8; j++)
#pragma unroll
            for (int c = 0; c < 4; c++) sacc[j][c] = 0.f;

#pragma unroll
        for (int ks = 0; ks < 4; ks++) {
            const int cb = ks * 16 + t4 * 2;
#pragma unroll
            for (int j = 0; j < 8; j++) {
                int n = j * 8 + g;
                uint32_t b0 = *(const uint32_t*)&Ks[n * HPAD + cb];
                uint32_t b1 = *(const uint32_t*)&Ks[n * HPAD + cb + 8];
                mma_f16(sacc[j], qf[ks], b0, b1);
            }
        }

        // epilogue: p = ex2(sacc)*inv -> att (.cs), pack to fp16 A-frags
        const size_t rowbase = (size_t)(m0 + rl) * SEQ + k0;
        uint32_t pk[8][2];
#pragma unroll
        for (int j = 0; j < 8; j++) {
            float p0 = ex2(sacc[j][0]) * inv_lo;
            float p1 = ex2(sacc[j][1]) * inv_lo;
            float p2 = ex2(sacc[j][2]) * inv_hi;
            float p3 = ex2(sacc[j][3]) * inv_hi;
            int cj = j * 8 + t4 * 2;
            stg_cs_v2(atth + rowbase + cj, p0, p1);
            stg_cs_v2(atth + rowbase + 8 * SEQ + cj, p2, p3);
            pk[j][0] = pack2(p0, p1);
            pk[j][1] = pack2(p2, p3);
        }

        // PV
#pragma unroll
        for (int kc = 0; kc < 4; kc++) {
            uint32_t A[4] = { pk[2 * kc][0], pk[2 * kc][1],
                              pk[2 * kc + 1][0], pk[2 * kc + 1][1] };
            const int kb = kc * 16 + t4 * 2;
#pragma unroll
            for (int jj = 0; jj < 8; jj++) {
                int nn = jj * 8 + g;
                uint32_t b0 = *(const uint32_t*)&Vs[nn * HPAD + kb];
                uint32_t b1 = *(const uint32_t*)&Vs[nn * HPAD + kb + 8];
                mma_f16(ctx[jj], A, b0, b1);
            }
        }
    }

    // store context
#pragma unroll
    for (int jj = 0; jj < 8; jj++) {
        int col = h * HD + jj * 8 + t4 * 2;
        *(float2*)(Ctx + (size_t)(m0 + rl) * (HQ * HD) + col) =
            make_float2(ctx[jj][0], ctx[jj][1]);
        *(float2*)(Ctx + (size_t)(m0 + rl + 8) * (HQ * HD) + col) =
            make_float2(ctx[jj][2], ctx[jj][3]);
    }
}

// ===========================================================================
// Projections (tf32 mma): C[M,N] = A[M,K] @ B[K,N] + bias
// ===========================================================================
#define PJ_AS 0
#define PJ_BS (128 * APAD)
#define PJ_SMEM_BYTES ((PJ_BS + 64 * BPAD) * 4)

__device__ __forceinline__ void proj_mma_stage(
    float* As, float* Bs, float acc[2][4][4],
    int wm, int wn, int g, int t4)
{
#pragma unroll
    for (int ks = 0; ks < 8; ks++) {
        const int kk = ks * 8;
        uint32_t Bf[4][2];
#pragma unroll
        for (int j = 0; j < 4; j++) {
            int n = wn * 32 + j * 8 + g;
            Bf[j][0] = fbits(Bs[(kk + t4) * BPAD + n]);
            Bf[j][1] = fbits(Bs[(kk + t4 + 4) * BPAD + n]);
        }
#pragma unroll
        for (int i = 0; i < 2; i++) {
            int r = wm * 32 + i * 16 + g;
            uint32_t Af[4] = {
                fbits(As[r * APAD + kk + t4]),
                fbits(As[(r + 8) * APAD + kk + t4]),
                fbits(As[r * APAD + kk + t4 + 4]),
                fbits(As[(r + 8) * APAD + kk + t4 + 4]) };
#pragma unroll
            for (int j = 0; j < 4; j++) mma_tf32(acc[i][j], Af, Bf[j]);
        }
    }
}

__device__ __forceinline__ void proj_epilogue(
    float acc[2][4][4], const float* bias, float* C, int ldc,
    int m0, int n0, int wm, int wn, int g, int t4)
{
#pragma unroll
    for (int i = 0; i < 2; i++) {
        int r0 = m0 + wm * 32 + i * 16 + g;
#pragma unroll
        for (int j = 0; j < 4; j++) {
            int col = n0 + wn * 32 + j * 8 + t4 * 2;
            float b0 = bias[col], b1 = bias[col + 1];
            *(float2*)(C + (size_t)r0 * ldc + col) =
                make_float2(acc[i][j][0] + b0, acc[i][j][1] + b1);
            *(float2*)(C + (size_t)(r0 + 8) * ldc + col) =
                make_float2(acc[i][j][2] + b0, acc[i][j][3] + b1);
        }
    }
}

__device__ __forceinline__ void proj_body(
    const float* __restrict__ A, int lda,
    const float* __restrict__ B, int ldb,
    const float* __restrict__ bias,
    float* __restrict__ C, int ldc, int Kdim, int m0, int n0)
{
    extern __shared__ float sm[];
    float* As = sm + PJ_AS;
    float* Bs = sm + PJ_BS;

    const int t = threadIdx.x, lane = t & 31, wid = t >> 5;
    const int wm = wid >> 1, wn = wid & 1;
    const int g = lane >> 2, t4 = lane & 3;

    float acc[2][4][4];
#pragma unroll
    for (int i = 0; i < 2; i++)
#pragma unroll
        for (int j = 0; j < 4; j++)
#pragma unroll
            for (int c = 0; c < 4; c++) acc[i][j][c] = 0.f;

    for (int k0 = 0; k0 < Kdim; k0 += 64) {
        float4 av[8];
#pragma unroll
        for (int i = 0; i < 8; i++) {
            int e = t + i * 256;
            int r = e >> 4, q = e & 15;
            av[i] = tf32x4(*(const float4*)(A + (size_t)(m0 + r) * lda + k0 + q * 4));
        }
        float4 bv[4];
#pragma unroll
        for (int i = 0; i < 4; i++) {
            int e = t + i * 256;
            int r = e >> 4, q = e & 15;
            bv[i] = tf32x4(*(const float4*)(B + (size_t)(k0 + r) * ldb + n0 + q * 4));
        }
        __syncthreads();
#pragma unroll
        for (int i = 0; i < 8; i++) {
            int e = t + i * 256;
            int r = e >> 4, q = e & 15;
            *(float4*)&As[r * APAD + q * 4] = av[i];
        }
#pragma unroll
        for (int i = 0; i < 4; i++) {
            int e = t + i * 256;
            int r = e >> 4, q = e & 15;
            *(float4*)&Bs[r * BPAD + q * 4] = bv[i];
        }
        __syncthreads();
        proj_mma_stage(As, Bs, acc, wm, wn, g, t4);
        __syncthreads();
    }
    proj_epilogue(acc, bias, C, ldc, m0, n0, wm, wn, g, t4);
}

__global__ __launch_bounds__(256, 2) void qkv_proj_kernel(
    const float* __restrict__ x,
    const float* __restrict__ Wq, const float* __restrict__ bq,
    const float* __restrict__ Wk, const float* __restrict__ bk,
    const float* __restrict__ Wv, const float* __restrict__ bv,
    float* __restrict__ Qo, float* __restrict__ Ko, float* __restrict__ Vo)
{
    const int seg = blockIdx.x;
    const int m0 = blockIdx.y * 128;
    const float *W, *bias;
    float* C;
    int ld, n0;
    if (seg < 8)       { W = Wq; bias = bq; C = Qo; ld = HQ * HD;  n0 = seg * 64; }
    else if (seg < 10) { W = Wk; bias = bk; C = Ko; ld = HKV * HD; n0 = (seg - 8) * 64; }
    else               { W = Wv; bias = bv; C = Vo; ld = HKV * HD; n0 = (seg - 10) * 64; }
    proj_body(x, DIMX, W, ld, bias, C, ld, DIMX, m0, n0);
}

__global__ __launch_bounds__(256, 2) void out_proj_kernel(
    const float* __restrict__ Ctx, const float* __restrict__ Wo,
    const float* __restrict__ bo, float* __restrict__ out)
{
    proj_body(Ctx, HQ * HD, Wo, DIMX, bo, out, DIMX, HQ * HD,
              blockIdx.y * 128, blockIdx.x * 64);
}

// ===========================================================================
extern "C" void kernel_launch(void* const* d_in, const int* in_sizes, int n_in,
                              void* d_out, int out_size)
{
    const float* x  = (const float*)d_in[0];
    const float* Wq = (const float*)d_in[1];
    const float* bq = (const float*)d_in[2];
    const float* Wk = (const float*)d_in[3];
    const float* bk = (const float*)d_in[4];
    const float* Wv = (const float*)d_in[5];
    const float* bv = (const float*)d_in[6];
    const float* Wo = (const float*)d_in[7];
    const float* bo = (const float*)d_in[8];

    float* out = (float*)d_out;                 // [4096, 768]
    float* att = out + (size_t)SEQ * DIMX;      // [8, 4096, 4096]

    void* p;
    cudaGetSymbolAddress(&p, g_Q);      float*  Qp  = (float*)p;
    cudaGetSymbolAddress(&p, g_K);      float*  Kp  = (float*)p;
    cudaGetSymbolAddress(&p, g_V);      float*  Vp  = (float*)p;
    cudaGetSymbolAddress(&p, g_Kh);     __half* Khp = (__half*)p;
    cudaGetSymbolAddress(&p, g_Vt);     __half* Vtp = (__half*)p;
    cudaGetSymbolAddress(&p, g_C);      float*  Cp  = (float*)p;
    cudaGetSymbolAddress(&p, g_rspart); float*  Rpp = (float*)p;

    cudaFuncSetAttribute(qkv_proj_kernel,
        cudaFuncAttributeMaxDynamicSharedMemorySize, PJ_SMEM_BYTES);
    cudaFuncSetAttribute(out_proj_kernel,
        cudaFuncAttributeMaxDynamicSharedMemorySize, PJ_SMEM_BYTES);

    // QKV projections
    qkv_proj_kernel<<<dim3(12, SEQ / 128), 256, PJ_SMEM_BYTES>>>(
        x, Wq, bq, Wk, bk, Wv, bv, Qp, Kp, Vp);

    // preps
    k2h_kernel<<<(SEQ * HKV * HD) / 4 / 256, 256>>>(Kp, Khp);
    vt_kernel<<<dim3(SEQ / 32, HD / 32, HKV), dim3(32, 8)>>>(Vp, Vtp);

    // Pass 1: partial rowsums (m-split 64 rows, 2-way key split)
    rowsum_kernel<<<dim3(SEQ / 64, HQ, RSPLIT), 128>>>(Qp, Khp, Rpp);

    // Pass 2: fused scores + softmax write + PV (m-split 64 rows, no k-split)
    fused_att_kernel<<<dim3(SEQ / 64, HQ), 128>>>(Qp, Khp, Vtp, Rpp, att, Cp);

    // out = ctx @ Wo + bo
    out_proj_kernel<<<dim3(DIMX / 64, SEQ / 128), 256, PJ_SMEM_BYTES>>>(
        Cp, Wo, bo, out);
}

// round 9
// speedup vs baseline: 1.0747x; 1.0077x over previous
#include <cuda_runtime.h>
#include <cuda_fp16.h>
#include <cstdint>

// Problem constants
#define DIMX 768
#define HQ   8
#define HKV  2
#define HD   64
#define SEQ  4096
#define NREP (HQ / HKV)   // 4
#define RSPLIT 2          // rowsum key split

// Scratch (allocation-free rule: __device__ globals)
__device__ float  g_Q[SEQ * HQ * HD];           // fp32
__device__ float  g_K[SEQ * HKV * HD];          // fp32
__device__ float  g_V[SEQ * HKV * HD];          // fp32
__device__ __half g_Kh[SEQ * HKV * HD];         // half, pair-interleaved d
__device__ __half g_Vt[HKV * HD * SEQ];         // [2][64][4096] half, transposed, pair-interleaved s
__device__ float  g_C[SEQ * HQ * HD];           // context
__device__ float  g_rspart[RSPLIT * HQ * SEQ];  // rowsum partials

// ===========================================================================
// helpers
// ===========================================================================
__device__ __forceinline__ float f2tf32(float x) {
    uint32_t u;
    asm("cvt.rna.tf32.f32 %0, %1;" : "=r"(u) : "f"(x));
    return __uint_as_float(u);
}
__device__ __forceinline__ float4 tf32x4(float4 v) {
    float4 w;
    w.x = f2tf32(v.x); w.y = f2tf32(v.y); w.z = f2tf32(v.z); w.w = f2tf32(v.w);
    return w;
}
__device__ __forceinline__ void mma_tf32(float* c, const uint32_t* a, const uint32_t* b) {
    asm volatile(
        "mma.sync.aligned.m16n8k8.row.col.f32.tf32.tf32.f32 "
        "{%0,%1,%2,%3}, {%4,%5,%6,%7}, {%8,%9}, {%0,%1,%2,%3};"
        : "+f"(c[0]), "+f"(c[1]), "+f"(c[2]), "+f"(c[3])
        : "r"(a[0]), "r"(a[1]), "r"(a[2]), "r"(a[3]), "r"(b[0]), "r"(b[1]));
}
__device__ __forceinline__ void mma_f16(float* c, const uint32_t* a, uint32_t b0, uint32_t b1) {
    asm volatile(
        "mma.sync.aligned.m16n8k16.row.col.f32.f16.f16.f32 "
        "{%0,%1,%2,%3}, {%4,%5,%6,%7}, {%8,%9}, {%0,%1,%2,%3};"
        : "+f"(c[0]), "+f"(c[1]), "+f"(c[2]), "+f"(c[3])
        : "r"(a[0]), "r"(a[1]), "r"(a[2]), "r"(a[3]), "r"(b0), "r"(b1));
}
__device__ __forceinline__ uint32_t pack2(float a, float b) {
    __half2 h = __floats2half2_rn(a, b);
    return *reinterpret_cast<uint32_t*>(&h);
}
__device__ __forceinline__ float ex2(float x) {
    float y;
    asm("ex2.approx.f32 %0, %1;" : "=f"(y) : "f"(x));
    return y;
}
__device__ __forceinline__ void stg_cs_v2(float* p, float a, float b) {
    asm volatile("st.global.cs.v2.f32 [%0], {%1, %2};"
                 :: "l"(p), "f"(a), "f"(b) : "memory");
}
__device__ __forceinline__ uint32_t fbits(float x) { return __float_as_uint(x); }

// scale baked into Q fragments: 1/sqrt(64) * log2(e)
#define QSCALE 0.1803368801111204f

#define APAD 68
#define BPAD 72
#define HPAD 80   // half tile stride (halves); conflict-free for LDS.64 frags

// ===========================================================================
// Prep: fp32 K -> half Kh with pair-interleaved d within each 16-group:
// positions [4u..4u+3] of a 16-chunk hold orig elements {2u,2u+1,2u+8,2u+9}.
// Thread -> one uint2 (4 halves).
// ===========================================================================
__global__ void k2h_kernel(const float* __restrict__ K, __half* __restrict__ Kh)
{
    int i = blockIdx.x * 256 + threadIdx.x;   // uint2 index
    int u = i & 3;
    int chunk = i >> 2;                        // 16-float chunk
    const float* src = K + (size_t)chunk * 16 + 2 * u;
    float2 lo = *(const float2*)src;
    float2 hi = *(const float2*)(src + 8);
    uint2 o;
    o.x = pack2(lo.x, lo.y);
    o.y = pack2(hi.x, hi.y);
    *(uint2*)((char*)Kh + (size_t)i * 8) = o;
}

// ===========================================================================
// Prep: fp32 V [s][kh*64+d] -> half Vt [kh][d][s_perm], s pair-interleaved
// within each 16-group.  P(s): 0,1->0,1  2,3->4,5  4,5->8,9  6,7->12,13
//                               8,9->2,3  10,11->6,7  12,13->10,11  14,15->14,15
// ===========================================================================
__device__ __forceinline__ int perm16(int s) {
    int q = s & 15;
    int p = (q < 8) ? ((q >> 1) * 4 + (q & 1))
                    : (((q - 8) >> 1) * 4 + 2 + (q & 1));
    return (s & ~15) | p;
}

__global__ void vt_kernel(const float* __restrict__ V, __half* __restrict__ Vt)
{
    __shared__ float tile[32][33];
    const int kh = blockIdx.z;
    const int s0 = blockIdx.x * 32;
    const int d0 = blockIdx.y * 32;
    const int tx = threadIdx.x, ty = threadIdx.y;
#pragma unroll
    for (int i = 0; i < 32; i += 8)
        tile[ty + i][tx] = V[(size_t)(s0 + ty + i) * (HKV * HD) + kh * HD + d0 + tx];
    __syncthreads();
#pragma unroll
    for (int i = 0; i < 32; i += 8)
        Vt[(size_t)kh * HD * SEQ + (size_t)(d0 + ty + i) * SEQ + s0 + perm16(tx)] =
            __float2half_rn(tile[tx][ty + i]);
}

// ===========================================================================
// Q fragment loader (16 rows per warp, scaled). Natural k-slot order.
// ===========================================================================
__device__ __forceinline__ void load_qfrag(
    uint32_t qf[4][4], const float* __restrict__ Q,
    int row0, int h, int g, int t4)
{
    const float* q0 = Q + (size_t)(row0 + g) * (HQ * HD) + h * HD;
    const float* q1 = q0 + (size_t)8 * (HQ * HD);
#pragma unroll
    for (int ks = 0; ks < 4; ks++) {
        int c = ks * 16 + t4 * 2;
        qf[ks][0] = pack2(q0[c] * QSCALE, q0[c + 1] * QSCALE);
        qf[ks][1] = pack2(q1[c] * QSCALE, q1[c + 1] * QSCALE);
        qf[ks][2] = pack2(q0[c + 8] * QSCALE, q0[c + 9] * QSCALE);
        qf[ks][3] = pack2(q1[c + 8] * QSCALE, q1[c + 9] * QSCALE);
    }
}

// B-fragment: one LDS.64 from pair-interleaved storage
__device__ __forceinline__ uint2 bfrag(const __half* base, int n, int ks, int t4) {
    return *(const uint2*)(base + n * HPAD + ks * 16 + t4 * 4);
}

// ===========================================================================
// Pass 1: partial rowsums. 128 thr, 4 warps x 16 rows. grid (SEQ/64, HQ, RSPLIT)
// ===========================================================================
__global__ __launch_bounds__(128) void rowsum_kernel(
    const float* __restrict__ Q, const __half* __restrict__ Kh,
    float* __restrict__ rspart)
{
    __shared__ __half Ks[128 * HPAD];

    const int t = threadIdx.x, lane = t & 31, wid = t >> 5;
    const int g = lane >> 2, t4 = lane & 3;
    const int m0 = blockIdx.x * 64, h = blockIdx.y, sp = blockIdx.z;
    const int kh = h / NREP;

    uint32_t qf[4][4];
    load_qfrag(qf, Q, m0 + wid * 16, h, g, t4);

    float rs0 = 0.f, rs1 = 0.f;
    const int it0 = sp * (SEQ / 128 / RSPLIT);
    const int it1 = it0 + (SEQ / 128 / RSPLIT);

    for (int it = it0; it < it1; it++) {
        const int n0 = it * 128;
        __syncthreads();
#pragma unroll
        for (int i = 0; i < 8; i++) {
            int e = t + i * 128;
            int r = e >> 3, seg = e & 7;
            *(uint4*)&Ks[r * HPAD + seg * 8] =
                *(const uint4*)(Kh + (size_t)(n0 + r) * (HKV * HD) + kh * HD + seg * 8);
        }
        __syncthreads();

#pragma unroll
        for (int jg = 0; jg < 2; jg++) {
            float sacc[8][4];
#pragma unroll
            for (int j = 0; j < 8; j++)
#pragma unroll
                for (int c = 0; c < 4; c++) sacc[j][c] = 0.f;
#pragma unroll
            for (int ks = 0; ks < 4; ks++) {
#pragma unroll
                for (int j = 0; j < 8; j++) {
                    uint2 b = bfrag(Ks, (jg * 8 + j) * 8 + g, ks, t4);
                    mma_f16(sacc[j], qf[ks], b.x, b.y);
                }
            }
#pragma unroll
            for (int j = 0; j < 8; j++) {
                rs0 += ex2(sacc[j][0]) + ex2(sacc[j][1]);
                rs1 += ex2(sacc[j][2]) + ex2(sacc[j][3]);
            }
        }
    }

    rs0 += __shfl_xor_sync(0xffffffffu, rs0, 1);
    rs0 += __shfl_xor_sync(0xffffffffu, rs0, 2);
    rs1 += __shfl_xor_sync(0xffffffffu, rs1, 1);
    rs1 += __shfl_xor_sync(0xffffffffu, rs1, 2);
    if (t4 == 0) {
        float* dst = rspart + (size_t)sp * HQ * SEQ + (size_t)h * SEQ + m0 + wid * 16;
        dst[g] = rs0;
        dst[g + 8] = rs1;
    }
}

// ===========================================================================
// Pass 2: fused scores + softmax write (.cs) + PV.
// 128 thr, 4 warps x 16 rows. grid (SEQ/64, HQ).
// ===========================================================================
__global__ __launch_bounds__(128) void fused_att_kernel(
    const float* __restrict__ Q, const __half* __restrict__ Kh,
    const __half* __restrict__ Vt, const float* __restrict__ rspart,
    float* __restrict__ att, float* __restrict__ Ctx)
{
    __shared__ __half Ks[64 * HPAD];
    __shared__ __half Vs[64 * HPAD];
    __shared__ float sinv[64];

    const int t = threadIdx.x, lane = t & 31, wid = t >> 5;
    const int g = lane >> 2, t4 = lane & 3;
    const int m0 = blockIdx.x * 64, h = blockIdx.y;
    const int kh = h / NREP;

    if (t < 64) {
        const float* rp = rspart + (size_t)h * SEQ + m0 + t;
        float s = rp[0];
#pragma unroll
        for (int i = 1; i < RSPLIT; i++) s += rp[(size_t)i * HQ * SEQ];
        sinv[t] = 1.0f / s;
    }

    uint32_t qf[4][4];
    load_qfrag(qf, Q, m0 + wid * 16, h, g, t4);
    __syncthreads();

    const int rl = wid * 16 + g;
    const float inv_lo = sinv[rl];
    const float inv_hi = sinv[rl + 8];
    const __half* vth = Vt + (size_t)kh * HD * SEQ;

    float ctx[8][4];
#pragma unroll
    for (int j = 0; j < 8; j++)
#pragma unroll
        for (int c = 0; c < 4; c++) ctx[j][c] = 0.f;

    float* atth = att + (size_t)h * SEQ * SEQ;

    for (int it = 0; it < SEQ / 64; it++) {
        const int k0 = it * 64;
        __syncthreads();
#pragma unroll
        for (int i = 0; i < 4; i++) {
            int e = t + i * 128;
            int r = e >> 3, seg = e & 7;
            *(uint4*)&Ks[r * HPAD + seg * 8] =
                *(const uint4*)(Kh + (size_t)(k0 + r) * (HKV * HD) + kh * HD + seg * 8);
            *(uint4*)&Vs[r * HPAD + seg * 8] =
                *(const uint4*)(vth + (size_t)r * SEQ + k0 + seg * 8);
        }
        __syncthreads();

        // scores: 16 rows x 64 keys
        float sacc[8][4];
#pragma unroll
        for (int j = 0; j < 8; j++)
#pragma unroll
            for (int c = 0; c < 4; c++) sacc[j][c] = 0.f;

#pragma unroll
        for (int ks = 0; ks < 4; ks++) {
#pragma unroll
            for (int j = 0; j < 8; j++) {
                uint2 b = bfrag(Ks, j * 8 + g, ks, t4);
                mma_f16(sacc[j], qf[ks], b.x, b.y);
            }
        }

        // epilogue: p = ex2(sacc)*inv -> att (.cs), pack to fp16 A-frags
        const size_t rowbase = (size_t)(m0 + rl) * SEQ + k0;
        uint32_t pk[8][2];
#pragma unroll
        for (int j = 0; j < 8; j++) {
            float p0 = ex2(sacc[j][0]) * inv_lo;
            float p1 = ex2(sacc[j][1]) * inv_lo;
            float p2 = ex2(sacc[j][2]) * inv_hi;
            float p3 = ex2(sacc[j][3]) * inv_hi;
            int cj = j * 8 + t4 * 2;
            stg_cs_v2(atth + rowbase + cj, p0, p1);
            stg_cs_v2(atth + rowbase + 8 * SEQ + cj, p2, p3);
            pk[j][0] = pack2(p0, p1);
            pk[j][1] = pack2(p2, p3);
        }

        // PV: A-frags = packed score C-frags (natural key slots)
#pragma unroll
        for (int kc = 0; kc < 4; kc++) {
            uint32_t A[4] = { pk[2 * kc][0], pk[2 * kc][1],
                              pk[2 * kc + 1][0], pk[2 * kc + 1][1] };
#pragma unroll
            for (int jj = 0; jj < 8; jj++) {
                uint2 b = bfrag(Vs, jj * 8 + g, kc, t4);
                mma_f16(ctx[jj], A, b.x, b.y);
            }
        }
    }

    // store context
#pragma unroll
    for (int jj = 0; jj < 8; jj++) {
        int col = h * HD + jj * 8 + t4 * 2;
        *(float2*)(Ctx + (size_t)(m0 + rl) * (HQ * HD) + col) =
            make_float2(ctx[jj][0], ctx[jj][1]);
        *(float2*)(Ctx + (size_t)(m0 + rl + 8) * (HQ * HD) + col) =
            make_float2(ctx[jj][2], ctx[jj][3]);
    }
}

// ===========================================================================
// Projections (tf32 mma): C[M,N] = A[M,K] @ B[K,N] + bias
// ===========================================================================
#define PJ_AS 0
#define PJ_BS (128 * APAD)
#define PJ_SMEM_BYTES ((PJ_BS + 64 * BPAD) * 4)

__device__ __forceinline__ void proj_mma_stage(
    float* As, float* Bs, float acc[2][4][4],
    int wm, int wn, int g, int t4)
{
#pragma unroll
    for (int ks = 0; ks < 8; ks++) {
        const int kk = ks * 8;
        uint32_t Bf[4][2];
#pragma unroll
        for (int j = 0; j < 4; j++) {
            int n = wn * 32 + j * 8 + g;
            Bf[j][0] = fbits(Bs[(kk + t4) * BPAD + n]);
            Bf[j][1] = fbits(Bs[(kk + t4 + 4) * BPAD + n]);
        }
#pragma unroll
        for (int i = 0; i < 2; i++) {
            int r = wm * 32 + i * 16 + g;
            uint32_t Af[4] = {
                fbits(As[r * APAD + kk + t4]),
                fbits(As[(r + 8) * APAD + kk + t4]),
                fbits(As[r * APAD + kk + t4 + 4]),
                fbits(As[(r + 8) * APAD + kk + t4 + 4]) };
#pragma unroll
            for (int j = 0; j < 4; j++) mma_tf32(acc[i][j], Af, Bf[j]);
        }
    }
}

__device__ __forceinline__ void proj_epilogue(
    float acc[2][4][4], const float* bias, float* C, int ldc,
    int m0, int n0, int wm, int wn, int g, int t4)
{
#pragma unroll
    for (int i = 0; i < 2; i++) {
        int r0 = m0 + wm * 32 + i * 16 + g;
#pragma unroll
        for (int j = 0; j < 4; j++) {
            int col = n0 + wn * 32 + j * 8 + t4 * 2;
            float b0 = bias[col], b1 = bias[col + 1];
            *(float2*)(C + (size_t)r0 * ldc + col) =
                make_float2(acc[i][j][0] + b0, acc[i][j][1] + b1);
            *(float2*)(C + (size_t)(r0 + 8) * ldc + col) =
                make_float2(acc[i][j][2] + b0, acc[i][j][3] + b1);
        }
    }
}

__device__ __forceinline__ void proj_body(
    const float* __restrict__ A, int lda,
    const float* __restrict__ B, int ldb,
    const float* __restrict__ bias,
    float* __restrict__ C, int ldc, int Kdim, int m0, int n0)
{
    extern __shared__ float sm[];
    float* As = sm + PJ_AS;
    float* Bs = sm + PJ_BS;

    const int t = threadIdx.x, lane = t & 31, wid = t >> 5;
    const int wm = wid >> 1, wn = wid & 1;
    const int g = lane >> 2, t4 = lane & 3;

    float acc[2][4][4];
#pragma unroll
    for (int i = 0; i < 2; i++)
#pragma unroll
        for (int j = 0; j < 4; j++)
#pragma unroll
            for (int c = 0; c < 4; c++) acc[i][j][c] = 0.f;

    for (int k0 = 0; k0 < Kdim; k0 += 64) {
        float4 av[8];
#pragma unroll
        for (int i = 0; i < 8; i++) {
            int e = t + i * 256;
            int r = e >> 4, q = e & 15;
            av[i] = tf32x4(*(const float4*)(A + (size_t)(m0 + r) * lda + k0 + q * 4));
        }
        float4 bv[4];
#pragma unroll
        for (int i = 0; i < 4; i++) {
            int e = t + i * 256;
            int r = e >> 4, q = e & 15;
            bv[i] = tf32x4(*(const float4*)(B + (size_t)(k0 + r) * ldb + n0 + q * 4));
        }
        __syncthreads();
#pragma unroll
        for (int i = 0; i < 8; i++) {
            int e = t + i * 256;
            int r = e >> 4, q = e & 15;
            *(float4*)&As[r * APAD + q * 4] = av[i];
        }
#pragma unroll
        for (int i = 0; i < 4; i++) {
            int e = t + i * 256;
            int r = e >> 4, q = e & 15;
            *(float4*)&Bs[r * BPAD + q * 4] = bv[i];
        }
        __syncthreads();
        proj_mma_stage(As, Bs, acc, wm, wn, g, t4);
        __syncthreads();
    }
    proj_epilogue(acc, bias, C, ldc, m0, n0, wm, wn, g, t4);
}

__global__ __launch_bounds__(256, 2) void qkv_proj_kernel(
    const float* __restrict__ x,
    const float* __restrict__ Wq, const float* __restrict__ bq,
    const float* __restrict__ Wk, const float* __restrict__ bk,
    const float* __restrict__ Wv, const float* __restrict__ bv,
    float* __restrict__ Qo, float* __restrict__ Ko, float* __restrict__ Vo)
{
    const int seg = blockIdx.x;
    const int m0 = blockIdx.y * 128;
    const float *W, *bias;
    float* C;
    int ld, n0;
    if (seg < 8)       { W = Wq; bias = bq; C = Qo; ld = HQ * HD;  n0 = seg * 64; }
    else if (seg < 10) { W = Wk; bias = bk; C = Ko; ld = HKV * HD; n0 = (seg - 8) * 64; }
    else               { W = Wv; bias = bv; C = Vo; ld = HKV * HD; n0 = (seg - 10) * 64; }
    proj_body(x, DIMX, W, ld, bias, C, ld, DIMX, m0, n0);
}

__global__ __launch_bounds__(256, 2) void out_proj_kernel(
    const float* __restrict__ Ctx, const float* __restrict__ Wo,
    const float* __restrict__ bo, float* __restrict__ out)
{
    proj_body(Ctx, HQ * HD, Wo, DIMX, bo, out, DIMX, HQ * HD,
              blockIdx.y * 128, blockIdx.x * 64);
}

// ===========================================================================
extern "C" void kernel_launch(void* const* d_in, const int* in_sizes, int n_in,
                              void* d_out, int out_size)
{
    const float* x  = (const float*)d_in[0];
    const float* Wq = (const float*)d_in[1];
    const float* bq = (const float*)d_in[2];
    const float* Wk = (const float*)d_in[3];
    const float* bk = (const float*)d_in[4];
    const float* Wv = (const float*)d_in[5];
    const float* bv = (const float*)d_in[6];
    const float* Wo = (const float*)d_in[7];
    const float* bo = (const float*)d_in[8];

    float* out = (float*)d_out;                 // [4096, 768]
    float* att = out + (size_t)SEQ * DIMX;      // [8, 4096, 4096]

    void* p;
    cudaGetSymbolAddress(&p, g_Q);      float*  Qp  = (float*)p;
    cudaGetSymbolAddress(&p, g_K);      float*  Kp  = (float*)p;
    cudaGetSymbolAddress(&p, g_V);      float*  Vp  = (float*)p;
    cudaGetSymbolAddress(&p, g_Kh);     __half* Khp = (__half*)p;
    cudaGetSymbolAddress(&p, g_Vt);     __half* Vtp = (__half*)p;
    cudaGetSymbolAddress(&p, g_C);      float*  Cp  = (float*)p;
    cudaGetSymbolAddress(&p, g_rspart); float*  Rpp = (float*)p;

    cudaFuncSetAttribute(qkv_proj_kernel,
        cudaFuncAttributeMaxDynamicSharedMemorySize, PJ_SMEM_BYTES);
    cudaFuncSetAttribute(out_proj_kernel,
        cudaFuncAttributeMaxDynamicSharedMemorySize, PJ_SMEM_BYTES);

    // QKV projections
    qkv_proj_kernel<<<dim3(12, SEQ / 128), 256, PJ_SMEM_BYTES>>>(
        x, Wq, bq, Wk, bk, Wv, bv, Qp, Kp, Vp);

    // preps (pair-interleaved layouts)
    k2h_kernel<<<(SEQ * HKV * HD) / 4 / 256, 256>>>(Kp, Khp);
    vt_kernel<<<dim3(SEQ / 32, HD / 32, HKV), dim3(32, 8)>>>(Vp, Vtp);

    // Pass 1: partial rowsums
    rowsum_kernel<<<dim3(SEQ / 64, HQ, RSPLIT), 128>>>(Qp, Khp, Rpp);

    // Pass 2: fused scores + softmax write + PV
    fused_att_kernel<<<dim3(SEQ / 64, HQ), 128>>>(Qp, Khp, Vtp, Rpp, att, Cp);

    // out = ctx @ Wo + bo
    out_proj_kernel<<<dim3(DIMX / 64, SEQ / 128), 256, PJ_SMEM_BYTES>>>(
        Cp, Wo, bo, out);
}